// round 1
// baseline (speedup 1.0000x reference)
#include <cuda_runtime.h>
#include <math.h>

// ---------------------------------------------------------------------------
// BondLengthHead: out[e] = softplus( relu( relu( [z[src]|z[dst]|emb[bt]] @ W1
//                               + b1) @ W2 + b2) @ W3 + b3 )
// Shapes: z[100000,128] f32, edge_index[2,E] i32/i64, bond_types[E] i32/i64,
//         embed[13,32], W1[288,128], b1[128], W2[128,64], b2[64], W3[64,1], b3[1]
// Output: [E] f32
// ---------------------------------------------------------------------------

#define TILE_E   64
#define NTHREADS 256
#define D_IN     288
#define N1       128
#define N2       64
#define FPAD     292   // smem row stride for F tile (4-float aligned, breaks bank pattern)
#define HPAD     132   // smem row stride for H1 tile
#define KC       32    // k-chunk for W1 staging

#define SMEM_FLOATS (TILE_E * FPAD + KC * N1)
#define SMEM_BYTES  (SMEM_FLOATS * 4)

__device__ int g_ei_is64;
__device__ int g_bt_is64;

// Detect int32 vs int64 storage: values are small non-negative, so if the
// buffer is little-endian int64, every odd int32 slot of the first entries is 0.
__global__ void detect_dtype_kernel(const int* __restrict__ ei,
                                    const int* __restrict__ bt) {
    if (threadIdx.x == 0 && blockIdx.x == 0) {
        int e64 = 1, b64 = 1;
        #pragma unroll 1
        for (int i = 0; i < 64; i++) {
            if (ei[2 * i + 1] != 0) { e64 = 0; break; }
        }
        #pragma unroll 1
        for (int i = 0; i < 64; i++) {
            if (bt[2 * i + 1] != 0) { b64 = 0; break; }
        }
        g_ei_is64 = e64;
        g_bt_is64 = b64;
    }
}

__device__ __forceinline__ float softplus_f(float x) {
    return fmaxf(x, 0.0f) + log1pf(expf(-fabsf(x)));
}

__global__ void __launch_bounds__(NTHREADS, 2)
bond_mlp_kernel(const float* __restrict__ z,
                const void*  __restrict__ eiv,
                const void*  __restrict__ btv,
                const float* __restrict__ embed,
                const float* __restrict__ W1,
                const float* __restrict__ b1,
                const float* __restrict__ W2,
                const float* __restrict__ b2,
                const float* __restrict__ W3,
                const float* __restrict__ b3,
                float* __restrict__ out,
                int E)
{
    extern __shared__ float smem[];
    float* sF = smem;                      // [TILE_E][FPAD], later aliased by sH
    float* sW = smem + TILE_E * FPAD;      // [KC][N1]
    __shared__ int sSrc[TILE_E];
    __shared__ int sDst[TILE_E];
    __shared__ int sBt[TILE_E];

    const int tid = threadIdx.x;
    const int tx  = tid & 15;   // 0..15 -> neuron group
    const int ty  = tid >> 4;   // 0..15 -> edge group
    const int e0  = ty * 4;     // local edge base for this thread
    const int eBase = blockIdx.x * TILE_E;

    const int ei64 = g_ei_is64;
    const int bt64 = g_bt_is64;

    // ---- stage edge indices ----
    if (tid < TILE_E) {
        int e = eBase + tid;
        int s = 0, d = 0, b = 0;
        if (e < E) {
            if (ei64) {
                const long long* p = (const long long*)eiv;
                s = (int)p[e];
                d = (int)p[(size_t)E + e];
            } else {
                const int* p = (const int*)eiv;
                s = p[e];
                d = p[(size_t)E + e];
            }
            if (bt64) b = (int)((const long long*)btv)[e];
            else      b = ((const int*)btv)[e];
        }
        sSrc[tid] = s; sDst[tid] = d; sBt[tid] = b;
    }
    __syncthreads();

    // ---- gather feature tile: 72 float4 per edge (32 src + 32 dst + 8 embed) ----
    {
        const float4* z4  = (const float4*)z;
        const float4* em4 = (const float4*)embed;
        for (int idx = tid; idx < TILE_E * 72; idx += NTHREADS) {
            int e = idx / 72;
            int c = idx - e * 72;
            float4 v;
            if (eBase + e >= E) {
                v = make_float4(0.f, 0.f, 0.f, 0.f);
            } else if (c < 32) {
                v = z4[(size_t)sSrc[e] * 32 + c];
            } else if (c < 64) {
                v = z4[(size_t)sDst[e] * 32 + (c - 32)];
            } else {
                v = em4[sBt[e] * 8 + (c - 64)];
            }
            *(float4*)&sF[e * FPAD + c * 4] = v;
        }
    }
    // (sync happens inside the first k-chunk iteration below)

    // ---- layer 1: H1[64,128] = relu(F @ W1 + b1) ----
    float acc[4][8];
    #pragma unroll
    for (int i = 0; i < 4; i++)
        #pragma unroll
        for (int j = 0; j < 8; j++) acc[i][j] = 0.0f;

    const float4* W1_4 = (const float4*)W1;  // 32 float4 per row
    for (int kk = 0; kk < D_IN; kk += KC) {
        __syncthreads();  // prev-chunk reads done (and gather writes visible on iter 0)
        #pragma unroll
        for (int r = 0; r < 4; r++) {
            int q = tid + r * NTHREADS;                  // 0..1023
            ((float4*)sW)[q] = W1_4[kk * (N1 / 4) + q];  // rows kk..kk+31
        }
        __syncthreads();
        #pragma unroll 8
        for (int k = 0; k < KC; k++) {
            float a0 = sF[(e0 + 0) * FPAD + kk + k];
            float a1 = sF[(e0 + 1) * FPAD + kk + k];
            float a2 = sF[(e0 + 2) * FPAD + kk + k];
            float a3 = sF[(e0 + 3) * FPAD + kk + k];
            float4 bA = *(const float4*)&sW[k * N1 + tx * 8];
            float4 bB = *(const float4*)&sW[k * N1 + tx * 8 + 4];
            acc[0][0] = fmaf(a0, bA.x, acc[0][0]); acc[0][1] = fmaf(a0, bA.y, acc[0][1]);
            acc[0][2] = fmaf(a0, bA.z, acc[0][2]); acc[0][3] = fmaf(a0, bA.w, acc[0][3]);
            acc[0][4] = fmaf(a0, bB.x, acc[0][4]); acc[0][5] = fmaf(a0, bB.y, acc[0][5]);
            acc[0][6] = fmaf(a0, bB.z, acc[0][6]); acc[0][7] = fmaf(a0, bB.w, acc[0][7]);
            acc[1][0] = fmaf(a1, bA.x, acc[1][0]); acc[1][1] = fmaf(a1, bA.y, acc[1][1]);
            acc[1][2] = fmaf(a1, bA.z, acc[1][2]); acc[1][3] = fmaf(a1, bA.w, acc[1][3]);
            acc[1][4] = fmaf(a1, bB.x, acc[1][4]); acc[1][5] = fmaf(a1, bB.y, acc[1][5]);
            acc[1][6] = fmaf(a1, bB.z, acc[1][6]); acc[1][7] = fmaf(a1, bB.w, acc[1][7]);
            acc[2][0] = fmaf(a2, bA.x, acc[2][0]); acc[2][1] = fmaf(a2, bA.y, acc[2][1]);
            acc[2][2] = fmaf(a2, bA.z, acc[2][2]); acc[2][3] = fmaf(a2, bA.w, acc[2][3]);
            acc[2][4] = fmaf(a2, bB.x, acc[2][4]); acc[2][5] = fmaf(a2, bB.y, acc[2][5]);
            acc[2][6] = fmaf(a2, bB.z, acc[2][6]); acc[2][7] = fmaf(a2, bB.w, acc[2][7]);
            acc[3][0] = fmaf(a3, bA.x, acc[3][0]); acc[3][1] = fmaf(a3, bA.y, acc[3][1]);
            acc[3][2] = fmaf(a3, bA.z, acc[3][2]); acc[3][3] = fmaf(a3, bA.w, acc[3][3]);
            acc[3][4] = fmaf(a3, bB.x, acc[3][4]); acc[3][5] = fmaf(a3, bB.y, acc[3][5]);
            acc[3][6] = fmaf(a3, bB.z, acc[3][6]); acc[3][7] = fmaf(a3, bB.w, acc[3][7]);
        }
    }
    __syncthreads();  // all sF reads done; safe to alias with sH

    // ---- relu + bias, write H1 tile (aliases sF) ----
    float* sH = smem;  // [TILE_E][HPAD]
    {
        float bb[8];
        #pragma unroll
        for (int j = 0; j < 8; j++) bb[j] = __ldg(&b1[tx * 8 + j]);
        #pragma unroll
        for (int i = 0; i < 4; i++) {
            float4 hA, hB;
            hA.x = fmaxf(acc[i][0] + bb[0], 0.f);
            hA.y = fmaxf(acc[i][1] + bb[1], 0.f);
            hA.z = fmaxf(acc[i][2] + bb[2], 0.f);
            hA.w = fmaxf(acc[i][3] + bb[3], 0.f);
            hB.x = fmaxf(acc[i][4] + bb[4], 0.f);
            hB.y = fmaxf(acc[i][5] + bb[5], 0.f);
            hB.z = fmaxf(acc[i][6] + bb[6], 0.f);
            hB.w = fmaxf(acc[i][7] + bb[7], 0.f);
            *(float4*)&sH[(e0 + i) * HPAD + tx * 8]     = hA;
            *(float4*)&sH[(e0 + i) * HPAD + tx * 8 + 4] = hB;
        }
    }
    __syncthreads();

    // ---- layer 2: H2[64,64] = relu(H1 @ W2 + b2), kept in registers ----
    float acc2[4][4];
    #pragma unroll
    for (int i = 0; i < 4; i++)
        #pragma unroll
        for (int j = 0; j < 4; j++) acc2[i][j] = 0.0f;

    const float4* W2_4 = (const float4*)W2;  // 16 float4 per row
    #pragma unroll 4
    for (int k = 0; k < N1; k++) {
        float a0 = sH[(e0 + 0) * HPAD + k];
        float a1 = sH[(e0 + 1) * HPAD + k];
        float a2 = sH[(e0 + 2) * HPAD + k];
        float a3 = sH[(e0 + 3) * HPAD + k];
        float4 b = __ldg(&W2_4[k * 16 + tx]);
        acc2[0][0] = fmaf(a0, b.x, acc2[0][0]); acc2[0][1] = fmaf(a0, b.y, acc2[0][1]);
        acc2[0][2] = fmaf(a0, b.z, acc2[0][2]); acc2[0][3] = fmaf(a0, b.w, acc2[0][3]);
        acc2[1][0] = fmaf(a1, b.x, acc2[1][0]); acc2[1][1] = fmaf(a1, b.y, acc2[1][1]);
        acc2[1][2] = fmaf(a1, b.z, acc2[1][2]); acc2[1][3] = fmaf(a1, b.w, acc2[1][3]);
        acc2[2][0] = fmaf(a2, b.x, acc2[2][0]); acc2[2][1] = fmaf(a2, b.y, acc2[2][1]);
        acc2[2][2] = fmaf(a2, b.z, acc2[2][2]); acc2[2][3] = fmaf(a2, b.w, acc2[2][3]);
        acc2[3][0] = fmaf(a3, b.x, acc2[3][0]); acc2[3][1] = fmaf(a3, b.y, acc2[3][1]);
        acc2[3][2] = fmaf(a3, b.z, acc2[3][2]); acc2[3][3] = fmaf(a3, b.w, acc2[3][3]);
    }

    // ---- layer 3: out = softplus(relu(H2) @ W3 + b3) via shuffle reduce ----
    {
        float w3v[4], b2v[4];
        #pragma unroll
        for (int j = 0; j < 4; j++) {
            w3v[j] = __ldg(&W3[tx * 4 + j]);
            b2v[j] = __ldg(&b2[tx * 4 + j]);
        }
        float bias3 = __ldg(b3);

        float part[4];
        #pragma unroll
        for (int i = 0; i < 4; i++) {
            float p = 0.f;
            #pragma unroll
            for (int j = 0; j < 4; j++) {
                float h = fmaxf(acc2[i][j] + b2v[j], 0.f);
                p = fmaf(h, w3v[j], p);
            }
            part[i] = p;
        }
        // reduce across tx (16 lanes per edge-group, 2 groups per warp)
        #pragma unroll
        for (int off = 8; off > 0; off >>= 1) {
            #pragma unroll
            for (int i = 0; i < 4; i++)
                part[i] += __shfl_down_sync(0xffffffffu, part[i], off, 16);
        }
        if (tx == 0) {
            #pragma unroll
            for (int i = 0; i < 4; i++) {
                int e = eBase + e0 + i;
                if (e < E) out[e] = softplus_f(part[i] + bias3);
            }
        }
    }
}

extern "C" void kernel_launch(void* const* d_in, const int* in_sizes, int n_in,
                              void* d_out, int out_size)
{
    const float* z     = (const float*)d_in[0];
    const void*  ei    = d_in[1];
    const void*  bt    = d_in[2];
    const float* embed = (const float*)d_in[3];
    const float* W1    = (const float*)d_in[4];
    const float* b1    = (const float*)d_in[5];
    const float* W2    = (const float*)d_in[6];
    const float* b2    = (const float*)d_in[7];
    const float* W3    = (const float*)d_in[8];
    const float* b3    = (const float*)d_in[9];
    float* out = (float*)d_out;

    int E = out_size;  // one output per edge

    cudaFuncSetAttribute(bond_mlp_kernel,
                         cudaFuncAttributeMaxDynamicSharedMemorySize, SMEM_BYTES);

    detect_dtype_kernel<<<1, 32>>>((const int*)ei, (const int*)bt);

    int blocks = (E + TILE_E - 1) / TILE_E;
    bond_mlp_kernel<<<blocks, NTHREADS, SMEM_BYTES>>>(
        z, ei, bt, embed, W1, b1, W2, b2, W3, b3, out, E);
}

// round 2
// speedup vs baseline: 3.5646x; 3.5646x over previous
#include <cuda_runtime.h>
#include <math.h>

// ---------------------------------------------------------------------------
// BondLengthHead, factorized:
//   P = z @ W1[0:128,:]      (per node, precomputed)
//   Q = z @ W1[128:256,:]    (per node, precomputed)
//   C = embed @ W1[256:288,:] + b1   (per bond type, 13x128)
//   h1 = relu(P[src] + Q[dst] + C[bt])          (per edge, gather+add)
//   h2 = relu(h1 @ W2 + b2); out = softplus(h2 @ W3 + b3)
// ---------------------------------------------------------------------------

#define MAXN     100000
#define N1       128
#define N2       64

// ---- scratch (allocation-free rule: __device__ globals) ----
__device__ float g_PQ[(size_t)MAXN * 256];   // [node][0:128]=P, [128:256]=Q
__device__ float g_C[13 * 128];
__device__ int   g_ei_is64;
__device__ int   g_bt_is64;

// ===========================================================================
// dtype detection (edge_index / bond_types may be stored as int64)
// ===========================================================================
__global__ void detect_dtype_kernel(const int* __restrict__ ei,
                                    const int* __restrict__ bt) {
    if (threadIdx.x == 0 && blockIdx.x == 0) {
        int e64 = 1, b64 = 1;
        #pragma unroll 1
        for (int i = 0; i < 64; i++) if (ei[2 * i + 1] != 0) { e64 = 0; break; }
        #pragma unroll 1
        for (int i = 0; i < 64; i++) if (bt[2 * i + 1] != 0) { b64 = 0; break; }
        g_ei_is64 = e64;
        g_bt_is64 = b64;
    }
}

// ===========================================================================
// C = embed @ W1[256:288,:] + b1   (13 x 128)
// ===========================================================================
__global__ void cemb_kernel(const float* __restrict__ embed,
                            const float* __restrict__ W1,
                            const float* __restrict__ b1) {
    int idx = blockIdx.x * 256 + threadIdx.x;
    if (idx < 13 * 128) {
        int t = idx >> 7, j = idx & 127;
        float s = b1[j];
        #pragma unroll
        for (int k = 0; k < 32; k++)
            s = fmaf(embed[t * 32 + k], W1[(256 + k) * 128 + j], s);
        g_C[idx] = s;
    }
}

// ===========================================================================
// Node GEMM: PQ[n][0:256] = z[n] @ [W1_top | W1_mid]
// Tile: 128 nodes x 64 cols per CTA, 256 threads, acc 8x4.
// ===========================================================================
#define GM   128
#define ZPAD 132
#define GEMM_SMEM ((GM * ZPAD + 32 * 64) * 4)

__global__ void __launch_bounds__(256)
node_gemm_kernel(const float* __restrict__ z,
                 const float* __restrict__ W1,
                 int nNodes)
{
    extern __shared__ float sm[];
    float* sZ = sm;              // [128][ZPAD]
    float* sW = sm + GM * ZPAD;  // [32][64]

    const int tid = threadIdx.x;
    const int tx  = tid & 15;    // col group: cols tx*4..+3
    const int ty  = tid >> 4;    // node group: nodes ty*8..+7
    const int m0  = blockIdx.x * GM;
    const int nt  = blockIdx.y;                // 0,1 -> P ; 2,3 -> Q
    const int krow = (nt >= 2) ? 128 : 0;      // weight row offset
    const int colb = (nt & 1) * 64;            // column base within half
    const int outb = krow + colb;              // output column base (0..192)

    // stage z tile [128][128]
    const float4* z4 = (const float4*)z;
    for (int i = tid; i < GM * 32; i += 256) {
        int r = i >> 5, c = i & 31;
        float4 v = make_float4(0.f, 0.f, 0.f, 0.f);
        if (m0 + r < nNodes) v = z4[(size_t)(m0 + r) * 32 + c];
        *(float4*)&sZ[r * ZPAD + c * 4] = v;
    }

    float acc[8][4];
    #pragma unroll
    for (int i = 0; i < 8; i++)
        #pragma unroll
        for (int j = 0; j < 4; j++) acc[i][j] = 0.f;

    for (int kk = 0; kk < 128; kk += 32) {
        __syncthreads();   // covers sZ stores on first iter, sW reads on later
        // stage W chunk: rows krow+kk..+31, cols colb..colb+63
        for (int i = tid; i < 32 * 16; i += 256) {
            int r = i >> 4, c = i & 15;
            ((float4*)sW)[i] = *(const float4*)&W1[(krow + kk + r) * 128 + colb + c * 4];
        }
        __syncthreads();

        #pragma unroll
        for (int k4 = 0; k4 < 8; k4++) {
            float4 b0 = *(const float4*)&sW[(k4 * 4 + 0) * 64 + tx * 4];
            float4 b1r = *(const float4*)&sW[(k4 * 4 + 1) * 64 + tx * 4];
            float4 b2r = *(const float4*)&sW[(k4 * 4 + 2) * 64 + tx * 4];
            float4 b3r = *(const float4*)&sW[(k4 * 4 + 3) * 64 + tx * 4];
            #pragma unroll
            for (int i = 0; i < 8; i++) {
                float4 a = *(const float4*)&sZ[(ty * 8 + i) * ZPAD + kk + k4 * 4];
                acc[i][0] = fmaf(a.x, b0.x,  acc[i][0]);
                acc[i][1] = fmaf(a.x, b0.y,  acc[i][1]);
                acc[i][2] = fmaf(a.x, b0.z,  acc[i][2]);
                acc[i][3] = fmaf(a.x, b0.w,  acc[i][3]);
                acc[i][0] = fmaf(a.y, b1r.x, acc[i][0]);
                acc[i][1] = fmaf(a.y, b1r.y, acc[i][1]);
                acc[i][2] = fmaf(a.y, b1r.z, acc[i][2]);
                acc[i][3] = fmaf(a.y, b1r.w, acc[i][3]);
                acc[i][0] = fmaf(a.z, b2r.x, acc[i][0]);
                acc[i][1] = fmaf(a.z, b2r.y, acc[i][1]);
                acc[i][2] = fmaf(a.z, b2r.z, acc[i][2]);
                acc[i][3] = fmaf(a.z, b2r.w, acc[i][3]);
                acc[i][0] = fmaf(a.w, b3r.x, acc[i][0]);
                acc[i][1] = fmaf(a.w, b3r.y, acc[i][1]);
                acc[i][2] = fmaf(a.w, b3r.z, acc[i][2]);
                acc[i][3] = fmaf(a.w, b3r.w, acc[i][3]);
            }
        }
    }

    // store
    #pragma unroll
    for (int i = 0; i < 8; i++) {
        int node = m0 + ty * 8 + i;
        if (node < nNodes) {
            float4 v = make_float4(acc[i][0], acc[i][1], acc[i][2], acc[i][3]);
            *(float4*)&g_PQ[(size_t)node * 256 + outb + tx * 4] = v;
        }
    }
}

// ===========================================================================
// Edge kernel: gather-add -> relu -> 128x64 GEMM -> relu -> 64x1 -> softplus
// 64 edges / CTA, 256 threads.
// ===========================================================================
#define TILE_E 64
#define HPAD   132
#define EDGE_SMEM ((TILE_E * HPAD + 128 * 64 + 13 * 128) * 4)

__device__ __forceinline__ float softplus_f(float x) {
    return fmaxf(x, 0.0f) + log1pf(expf(-fabsf(x)));
}

__global__ void __launch_bounds__(256)
edge_kernel(const void*  __restrict__ eiv,
            const void*  __restrict__ btv,
            const float* __restrict__ W2,
            const float* __restrict__ b2,
            const float* __restrict__ W3,
            const float* __restrict__ b3,
            float* __restrict__ out,
            int E)
{
    extern __shared__ float sm[];
    float* sH  = sm;                           // [64][HPAD]
    float* sW2 = sm + TILE_E * HPAD;           // [128][64]
    float* sC  = sW2 + 128 * 64;               // [13][128]
    __shared__ int sSrc[TILE_E], sDst[TILE_E], sBt[TILE_E];

    const int tid = threadIdx.x;
    const int tx  = tid & 15;     // neuron group: n = tx*4..+3
    const int ty  = tid >> 4;     // edge group:   e = ty*4..+3
    const int e0  = ty * 4;
    const int eBase = blockIdx.x * TILE_E;
    const int ei64 = g_ei_is64, bt64 = g_bt_is64;

    // stage W2 (32KB) and C (6.5KB)
    for (int i = tid; i < 128 * 16; i += 256)
        ((float4*)sW2)[i] = ((const float4*)W2)[i];
    for (int i = tid; i < 13 * 32; i += 256)
        ((float4*)sC)[i] = ((const float4*)g_C)[i];

    // stage indices
    if (tid < TILE_E) {
        int e = eBase + tid;
        int s = 0, d = 0, b = 0;
        if (e < E) {
            if (ei64) {
                const long long* p = (const long long*)eiv;
                s = (int)p[e]; d = (int)p[(size_t)E + e];
            } else {
                const int* p = (const int*)eiv;
                s = p[e]; d = p[(size_t)E + e];
            }
            if (bt64) b = (int)((const long long*)btv)[e];
            else      b = ((const int*)btv)[e];
        }
        sSrc[tid] = s; sDst[tid] = d; sBt[tid] = b;
    }
    __syncthreads();

    // gather + add + relu -> sH  (warp i handles whole rows: coalesced 512B)
    {
        const float4* PQ4 = (const float4*)g_PQ;
        const float4* sC4 = (const float4*)sC;
        for (int idx = tid; idx < TILE_E * 32; idx += 256) {
            int e = idx >> 5;        // local edge
            int c = idx & 31;        // float4 column (0..31)
            float4 p = PQ4[(size_t)sSrc[e] * 64 + c];        // P[src][c]
            float4 q = PQ4[(size_t)sDst[e] * 64 + 32 + c];   // Q[dst][c]
            float4 cc = sC4[sBt[e] * 32 + c];
            float4 h;
            h.x = fmaxf(p.x + q.x + cc.x, 0.f);
            h.y = fmaxf(p.y + q.y + cc.y, 0.f);
            h.z = fmaxf(p.z + q.z + cc.z, 0.f);
            h.w = fmaxf(p.w + q.w + cc.w, 0.f);
            *(float4*)&sH[e * HPAD + c * 4] = h;
        }
    }
    __syncthreads();

    // layer 2: H2[64][64], acc 4 edges x 4 neurons, vectorized k
    float acc2[4][4];
    #pragma unroll
    for (int i = 0; i < 4; i++)
        #pragma unroll
        for (int j = 0; j < 4; j++) acc2[i][j] = 0.f;

    #pragma unroll 4
    for (int k4 = 0; k4 < 32; k4++) {
        float a[4][4];
        #pragma unroll
        for (int i = 0; i < 4; i++) {
            float4 av = *(const float4*)&sH[(e0 + i) * HPAD + k4 * 4];
            a[i][0] = av.x; a[i][1] = av.y; a[i][2] = av.z; a[i][3] = av.w;
        }
        #pragma unroll
        for (int q = 0; q < 4; q++) {
            float4 b = *(const float4*)&sW2[(k4 * 4 + q) * 64 + tx * 4];
            #pragma unroll
            for (int i = 0; i < 4; i++) {
                acc2[i][0] = fmaf(a[i][q], b.x, acc2[i][0]);
                acc2[i][1] = fmaf(a[i][q], b.y, acc2[i][1]);
                acc2[i][2] = fmaf(a[i][q], b.z, acc2[i][2]);
                acc2[i][3] = fmaf(a[i][q], b.w, acc2[i][3]);
            }
        }
    }

    // layer 3 + softplus
    {
        float w3v[4], b2v[4];
        #pragma unroll
        for (int j = 0; j < 4; j++) {
            w3v[j] = __ldg(&W3[tx * 4 + j]);
            b2v[j] = __ldg(&b2[tx * 4 + j]);
        }
        float bias3 = __ldg(b3);

        float part[4];
        #pragma unroll
        for (int i = 0; i < 4; i++) {
            float p = 0.f;
            #pragma unroll
            for (int j = 0; j < 4; j++) {
                float h = fmaxf(acc2[i][j] + b2v[j], 0.f);
                p = fmaf(h, w3v[j], p);
            }
            part[i] = p;
        }
        #pragma unroll
        for (int off = 8; off > 0; off >>= 1)
            #pragma unroll
            for (int i = 0; i < 4; i++)
                part[i] += __shfl_down_sync(0xffffffffu, part[i], off, 16);
        if (tx == 0) {
            #pragma unroll
            for (int i = 0; i < 4; i++) {
                int e = eBase + e0 + i;
                if (e < E) out[e] = softplus_f(part[i] + bias3);
            }
        }
    }
}

// ===========================================================================
extern "C" void kernel_launch(void* const* d_in, const int* in_sizes, int n_in,
                              void* d_out, int out_size)
{
    const float* z     = (const float*)d_in[0];
    const void*  ei    = d_in[1];
    const void*  bt    = d_in[2];
    const float* embed = (const float*)d_in[3];
    const float* W1    = (const float*)d_in[4];
    const float* b1    = (const float*)d_in[5];
    const float* W2    = (const float*)d_in[6];
    const float* b2    = (const float*)d_in[7];
    const float* W3    = (const float*)d_in[8];
    const float* b3    = (const float*)d_in[9];
    float* out = (float*)d_out;

    int nNodes = in_sizes[0] / 128;
    int E = out_size;

    static int attr_done = 0;
    if (!attr_done) {
        cudaFuncSetAttribute(node_gemm_kernel,
                             cudaFuncAttributeMaxDynamicSharedMemorySize, GEMM_SMEM);
        cudaFuncSetAttribute(edge_kernel,
                             cudaFuncAttributeMaxDynamicSharedMemorySize, EDGE_SMEM);
        attr_done = 1;
    }

    detect_dtype_kernel<<<1, 32>>>((const int*)ei, (const int*)bt);
    cemb_kernel<<<7, 256>>>(embed, W1, b1);

    dim3 ggrid((nNodes + GM - 1) / GM, 4);
    node_gemm_kernel<<<ggrid, 256, GEMM_SMEM>>>(z, W1, nNodes);

    int eblocks = (E + TILE_E - 1) / TILE_E;
    edge_kernel<<<eblocks, 256, EDGE_SMEM>>>(ei, bt, W2, b2, W3, b3, out, E);
}

// round 4
// speedup vs baseline: 5.3662x; 1.5054x over previous
#include <cuda_runtime.h>
#include <cuda_bf16.h>
#include <math.h>
#include <stdint.h>

// ---------------------------------------------------------------------------
// BondLengthHead, factorized; layer 2 on mma.sync (bf16 split, f32 accum):
//   P = z @ W1[0:128,:], Q = z @ W1[128:256,:]   (per node, SIMT GEMM)
//   C = embed @ W1[256:288,:] + b1               (13x128)
//   per 128-edge tile: g = relu(P[src]+Q[dst]+C[bt]) -> split bf16 hi/lo
//   D = Ahi Bhi + Ahi Blo + Alo Bhi  (m16n8k16 HMMA, f32 acc)
//   out = softplus(relu(D + b2) . W3 + b3)
// NOTE: harness compiles via compute_103 (no 'a') -> no tcgen05/TMEM allowed.
// ---------------------------------------------------------------------------

#define MAXN 100000

__device__ float g_PQ[(size_t)MAXN * 256];
__device__ float g_C[13 * 128];
__device__ int   g_ei_is64;
__device__ int   g_bt_is64;

__device__ __forceinline__ uint32_t smem_u32(const void* p) {
    uint32_t a;
    asm("{ .reg .u64 t; cvta.to.shared.u64 t, %1; cvt.u32.u64 %0, t; }"
        : "=r"(a) : "l"(p));
    return a;
}

__device__ __forceinline__ void ldsm_x4(uint32_t* r, uint32_t addr) {
    asm volatile("ldmatrix.sync.aligned.m8n8.x4.shared.b16 {%0,%1,%2,%3}, [%4];"
                 : "=r"(r[0]), "=r"(r[1]), "=r"(r[2]), "=r"(r[3]) : "r"(addr));
}

__device__ __forceinline__ void mma_bf16(float* d, const uint32_t* a,
                                         uint32_t b0, uint32_t b1) {
    asm volatile("mma.sync.aligned.m16n8k16.row.col.f32.bf16.bf16.f32 "
                 "{%0,%1,%2,%3}, {%4,%5,%6,%7}, {%8,%9}, {%0,%1,%2,%3};"
                 : "+f"(d[0]), "+f"(d[1]), "+f"(d[2]), "+f"(d[3])
                 : "r"(a[0]), "r"(a[1]), "r"(a[2]), "r"(a[3]),
                   "r"(b0), "r"(b1));
}

__device__ __forceinline__ float softplus_f(float x) {
    return fmaxf(x, 0.0f) + log1pf(expf(-fabsf(x)));
}

// ===========================================================================
__global__ void detect_dtype_kernel(const int* __restrict__ ei,
                                    const int* __restrict__ bt) {
    if (threadIdx.x == 0 && blockIdx.x == 0) {
        int e64 = 1, b64 = 1;
        #pragma unroll 1
        for (int i = 0; i < 64; i++) if (ei[2 * i + 1] != 0) { e64 = 0; break; }
        #pragma unroll 1
        for (int i = 0; i < 64; i++) if (bt[2 * i + 1] != 0) { b64 = 0; break; }
        g_ei_is64 = e64;
        g_bt_is64 = b64;
    }
}

__global__ void cemb_kernel(const float* __restrict__ embed,
                            const float* __restrict__ W1,
                            const float* __restrict__ b1) {
    int idx = blockIdx.x * 256 + threadIdx.x;
    if (idx < 13 * 128) {
        int t = idx >> 7, j = idx & 127;
        float s = b1[j];
        #pragma unroll
        for (int k = 0; k < 32; k++)
            s = fmaf(embed[t * 32 + k], W1[(256 + k) * 128 + j], s);
        g_C[idx] = s;
    }
}

// ===========================================================================
// Node GEMM (unchanged): PQ = z @ [W1_top | W1_mid]
// ===========================================================================
#define GM   128
#define ZPAD 132
#define GEMM_SMEM ((GM * ZPAD + 32 * 64) * 4)

__global__ void __launch_bounds__(256)
node_gemm_kernel(const float* __restrict__ z,
                 const float* __restrict__ W1,
                 int nNodes)
{
    extern __shared__ float sm[];
    float* sZ = sm;
    float* sW = sm + GM * ZPAD;

    const int tid = threadIdx.x;
    const int tx  = tid & 15;
    const int ty  = tid >> 4;
    const int m0  = blockIdx.x * GM;
    const int nt  = blockIdx.y;
    const int krow = (nt >= 2) ? 128 : 0;
    const int colb = (nt & 1) * 64;
    const int outb = krow + colb;

    const float4* z4 = (const float4*)z;
    for (int i = tid; i < GM * 32; i += 256) {
        int r = i >> 5, c = i & 31;
        float4 v = make_float4(0.f, 0.f, 0.f, 0.f);
        if (m0 + r < nNodes) v = z4[(size_t)(m0 + r) * 32 + c];
        *(float4*)&sZ[r * ZPAD + c * 4] = v;
    }

    float acc[8][4];
    #pragma unroll
    for (int i = 0; i < 8; i++)
        #pragma unroll
        for (int j = 0; j < 4; j++) acc[i][j] = 0.f;

    for (int kk = 0; kk < 128; kk += 32) {
        __syncthreads();
        for (int i = tid; i < 32 * 16; i += 256) {
            int r = i >> 4, c = i & 15;
            ((float4*)sW)[i] = *(const float4*)&W1[(krow + kk + r) * 128 + colb + c * 4];
        }
        __syncthreads();
        #pragma unroll
        for (int k4 = 0; k4 < 8; k4++) {
            float4 b0  = *(const float4*)&sW[(k4 * 4 + 0) * 64 + tx * 4];
            float4 b1r = *(const float4*)&sW[(k4 * 4 + 1) * 64 + tx * 4];
            float4 b2r = *(const float4*)&sW[(k4 * 4 + 2) * 64 + tx * 4];
            float4 b3r = *(const float4*)&sW[(k4 * 4 + 3) * 64 + tx * 4];
            #pragma unroll
            for (int i = 0; i < 8; i++) {
                float4 a = *(const float4*)&sZ[(ty * 8 + i) * ZPAD + kk + k4 * 4];
                acc[i][0] = fmaf(a.x, b0.x,  acc[i][0]);
                acc[i][1] = fmaf(a.x, b0.y,  acc[i][1]);
                acc[i][2] = fmaf(a.x, b0.z,  acc[i][2]);
                acc[i][3] = fmaf(a.x, b0.w,  acc[i][3]);
                acc[i][0] = fmaf(a.y, b1r.x, acc[i][0]);
                acc[i][1] = fmaf(a.y, b1r.y, acc[i][1]);
                acc[i][2] = fmaf(a.y, b1r.z, acc[i][2]);
                acc[i][3] = fmaf(a.y, b1r.w, acc[i][3]);
                acc[i][0] = fmaf(a.z, b2r.x, acc[i][0]);
                acc[i][1] = fmaf(a.z, b2r.y, acc[i][1]);
                acc[i][2] = fmaf(a.z, b2r.z, acc[i][2]);
                acc[i][3] = fmaf(a.z, b2r.w, acc[i][3]);
                acc[i][0] = fmaf(a.w, b3r.x, acc[i][0]);
                acc[i][1] = fmaf(a.w, b3r.y, acc[i][1]);
                acc[i][2] = fmaf(a.w, b3r.z, acc[i][2]);
                acc[i][3] = fmaf(a.w, b3r.w, acc[i][3]);
            }
        }
    }

    #pragma unroll
    for (int i = 0; i < 8; i++) {
        int node = m0 + ty * 8 + i;
        if (node < nNodes) {
            float4 v = make_float4(acc[i][0], acc[i][1], acc[i][2], acc[i][3]);
            *(float4*)&g_PQ[(size_t)node * 256 + outb + tx * 4] = v;
        }
    }
}

// ===========================================================================
// Edge kernel: persistent, mma.sync layer 2
// ===========================================================================
#define ETILE  128
#define ROWB   272                       // row stride bytes (136 bf16): conflict-free ldmatrix
#define OFF_AHI  0
#define OFF_ALO  (OFF_AHI + 128 * ROWB)  // 34816
#define OFF_WHI  (OFF_ALO + 128 * ROWB)  // 69632
#define OFF_WLO  (OFF_WHI + 64 * ROWB)   // 87040
#define OFF_C    (OFF_WLO + 64 * ROWB)   // 104448
#define OFF_BW   (OFF_C + 13 * 128 * 4)  // 111104
#define OFF_IDX  (OFF_BW + 64 * 8)       // 111616
#define EDGE_SMEM (OFF_IDX + 3 * ETILE * 4)  // 113152

__global__ void __launch_bounds__(256, 2)
edge_mma_kernel(const void*  __restrict__ eiv,
                const void*  __restrict__ btv,
                const float* __restrict__ W2,
                const float* __restrict__ b2,
                const float* __restrict__ W3,
                const float* __restrict__ b3,
                float* __restrict__ out,
                int E, int nTiles)
{
    extern __shared__ char sb[];
    const uint32_t base = smem_u32(sb);

    char*   Ahi = sb + OFF_AHI;
    char*   Alo = sb + OFF_ALO;
    char*   Whi = sb + OFF_WHI;
    char*   Wlo = sb + OFF_WLO;
    float*  sC  = (float*)(sb + OFF_C);
    float2* sBW = (float2*)(sb + OFF_BW);
    int*    sSrc = (int*)(sb + OFF_IDX);
    int*    sDst = sSrc + ETILE;
    int*    sBt  = sDst + ETILE;

    const int tid  = threadIdx.x;
    const int wid  = tid >> 5;
    const int lane = tid & 31;
    const int g    = lane >> 2;
    const int tg   = lane & 3;
    const int ei64 = g_ei_is64, bt64 = g_bt_is64;

    // ---- one-time staging ----
    for (int i = tid; i < 13 * 32; i += 256)
        ((float4*)sC)[i] = ((const float4*)g_C)[i];
    if (tid < 64) sBW[tid] = make_float2(b2[tid], W3[tid]);
    for (int i = tid; i < 128 * 64; i += 256) {
        int k = i >> 6, n = i & 63;
        float w = W2[i];
        __nv_bfloat16 hi = __float2bfloat16(w);
        float lof = w - __bfloat162float(hi);
        uint32_t off = (uint32_t)n * ROWB + (uint32_t)k * 2;
        *(__nv_bfloat16*)(Whi + off) = hi;
        *(__nv_bfloat16*)(Wlo + off) = __float2bfloat16(lof);
    }
    __syncthreads();

    const float b3v = __ldg(b3);

    // per-lane ldmatrix row offset (same formula for A and W2T tiles)
    const uint32_t rowoff = (uint32_t)(((lane & 7) + ((lane & 8) ? 8 : 0)) * ROWB
                                       + ((lane & 16) ? 16 : 0));
    const uint32_t aHiBase = base + OFF_AHI + (uint32_t)(wid * 16) * ROWB + rowoff;
    const uint32_t aLoBase = base + OFF_ALO + (uint32_t)(wid * 16) * ROWB + rowoff;
    const uint32_t wHiBase = base + OFF_WHI + rowoff;
    const uint32_t wLoBase = base + OFF_WLO + rowoff;

    const float4* PQ4 = (const float4*)g_PQ;

    for (int tile = blockIdx.x; tile < nTiles; tile += gridDim.x) {
        const int eBase = tile * ETILE;

        // ---- indices ----
        if (tid < ETILE) {
            int e = eBase + tid;
            int s = 0, d = 0, b = 0;
            if (e < E) {
                if (ei64) {
                    const long long* p = (const long long*)eiv;
                    s = (int)p[e]; d = (int)p[(size_t)E + e];
                } else {
                    const int* p = (const int*)eiv;
                    s = p[e]; d = p[(size_t)E + e];
                }
                if (bt64) b = (int)((const long long*)btv)[e];
                else      b = ((const int*)btv)[e];
            }
            sSrc[tid] = s; sDst[tid] = d; sBt[tid] = b;
        }
        __syncthreads();

        // ---- gather + relu + bf16 split into A tiles ----
        // idx: e = idx>>5 (edge row), c = idx&31 (float4 column)
        #pragma unroll 4
        for (int idx = tid; idx < ETILE * 32; idx += 256) {
            int e = idx >> 5, c = idx & 31;
            float4 p = PQ4[(size_t)sSrc[e] * 64 + c];
            float4 q = PQ4[(size_t)sDst[e] * 64 + 32 + c];
            float4 cc = ((const float4*)(sC + sBt[e] * 128))[c];
            float g0 = fmaxf(p.x + q.x + cc.x, 0.f);
            float g1 = fmaxf(p.y + q.y + cc.y, 0.f);
            float g2 = fmaxf(p.z + q.z + cc.z, 0.f);
            float g3 = fmaxf(p.w + q.w + cc.w, 0.f);
            union { uint2 u; __nv_bfloat16 h[4]; } ph, pl;
            ph.h[0] = __float2bfloat16(g0);
            ph.h[1] = __float2bfloat16(g1);
            ph.h[2] = __float2bfloat16(g2);
            ph.h[3] = __float2bfloat16(g3);
            pl.h[0] = __float2bfloat16(g0 - __bfloat162float(ph.h[0]));
            pl.h[1] = __float2bfloat16(g1 - __bfloat162float(ph.h[1]));
            pl.h[2] = __float2bfloat16(g2 - __bfloat162float(ph.h[2]));
            pl.h[3] = __float2bfloat16(g3 - __bfloat162float(ph.h[3]));
            uint32_t off = (uint32_t)e * ROWB + (uint32_t)c * 8;
            *(uint2*)(Ahi + off) = ph.u;
            *(uint2*)(Alo + off) = pl.u;
        }
        __syncthreads();

        // ---- layer 2 MMAs: warp wid owns edges 16*wid..+15, all 64 n ----
        float D[8][4];
        #pragma unroll
        for (int i = 0; i < 8; i++)
            #pragma unroll
            for (int j = 0; j < 4; j++) D[i][j] = 0.f;

        #pragma unroll
        for (int ks = 0; ks < 8; ks++) {
            uint32_t ah[4], al[4];
            ldsm_x4(ah, aHiBase + ks * 32);
            ldsm_x4(al, aLoBase + ks * 32);
            #pragma unroll
            for (int p = 0; p < 4; p++) {
                uint32_t bh[4], bl[4];
                ldsm_x4(bh, wHiBase + (uint32_t)(p * 16) * ROWB + ks * 32);
                ldsm_x4(bl, wLoBase + (uint32_t)(p * 16) * ROWB + ks * 32);
                mma_bf16(D[2 * p],     ah, bh[0], bh[2]);
                mma_bf16(D[2 * p],     ah, bl[0], bl[2]);
                mma_bf16(D[2 * p],     al, bh[0], bh[2]);
                mma_bf16(D[2 * p + 1], ah, bh[1], bh[3]);
                mma_bf16(D[2 * p + 1], ah, bl[1], bl[3]);
                mma_bf16(D[2 * p + 1], al, bh[1], bh[3]);
            }
        }

        // ---- layer 3 + softplus ----
        // thread owns edges (16*wid+g) via d0/d1 and (+8) via d2/d3;
        // cols n = nt*8 + tg*2 + {0,1}
        {
            float p0 = 0.f, p1 = 0.f;
            #pragma unroll
            for (int nt = 0; nt < 8; nt++) {
                int n = nt * 8 + tg * 2;
                float2 bw0 = sBW[n];
                float2 bw1 = sBW[n + 1];
                p0 = fmaf(fmaxf(D[nt][0] + bw0.x, 0.f), bw0.y, p0);
                p0 = fmaf(fmaxf(D[nt][1] + bw1.x, 0.f), bw1.y, p0);
                p1 = fmaf(fmaxf(D[nt][2] + bw0.x, 0.f), bw0.y, p1);
                p1 = fmaf(fmaxf(D[nt][3] + bw1.x, 0.f), bw1.y, p1);
            }
            p0 += __shfl_xor_sync(0xffffffffu, p0, 1);
            p0 += __shfl_xor_sync(0xffffffffu, p0, 2);
            p1 += __shfl_xor_sync(0xffffffffu, p1, 1);
            p1 += __shfl_xor_sync(0xffffffffu, p1, 2);
            if (tg == 0) {
                int e0 = eBase + wid * 16 + g;
                if (e0 < E)     out[e0]     = softplus_f(p0 + b3v);
                if (e0 + 8 < E) out[e0 + 8] = softplus_f(p1 + b3v);
            }
        }
        __syncthreads();   // A consumed by all warps; safe to overwrite next tile
    }
}

// ===========================================================================
extern "C" void kernel_launch(void* const* d_in, const int* in_sizes, int n_in,
                              void* d_out, int out_size)
{
    const float* z     = (const float*)d_in[0];
    const void*  ei    = d_in[1];
    const void*  bt    = d_in[2];
    const float* embed = (const float*)d_in[3];
    const float* W1    = (const float*)d_in[4];
    const float* b1    = (const float*)d_in[5];
    const float* W2    = (const float*)d_in[6];
    const float* b2    = (const float*)d_in[7];
    const float* W3    = (const float*)d_in[8];
    const float* b3    = (const float*)d_in[9];
    float* out = (float*)d_out;

    int nNodes = in_sizes[0] / 128;
    int E = out_size;
    int nTiles = (E + ETILE - 1) / ETILE;

    static int attr_done = 0;
    if (!attr_done) {
        cudaFuncSetAttribute(node_gemm_kernel,
                             cudaFuncAttributeMaxDynamicSharedMemorySize, GEMM_SMEM);
        cudaFuncSetAttribute(edge_mma_kernel,
                             cudaFuncAttributeMaxDynamicSharedMemorySize, EDGE_SMEM);
        attr_done = 1;
    }

    detect_dtype_kernel<<<1, 32>>>((const int*)ei, (const int*)bt);
    cemb_kernel<<<7, 256>>>(embed, W1, b1);

    dim3 ggrid((nNodes + GM - 1) / GM, 4);
    node_gemm_kernel<<<ggrid, 256, GEMM_SMEM>>>(z, W1, nNodes);

    int eg = nTiles < 296 ? nTiles : 296;
    edge_mma_kernel<<<eg, 256, EDGE_SMEM>>>(ei, bt, W2, b2, W3, b3, out, E, nTiles);
}

// round 5
// speedup vs baseline: 7.0120x; 1.3067x over previous
#include <cuda_runtime.h>
#include <cuda_bf16.h>
#include <math.h>
#include <stdint.h>

// ---------------------------------------------------------------------------
// BondLengthHead, fully tensorized (mma.sync bf16 split, f32 accum):
//   P = z @ W1[0:128,:], Q = z @ W1[128:256,:]   (node_mma_kernel, HMMA)
//   C = embed @ W1[256:288,:] + b1               (13x128)
//   per 128-edge tile: g = relu(P[src]+Q[dst]+C[bt]) -> split bf16 hi/lo
//   D = Ahi Bhi + Ahi Blo + Alo Bhi  (m16n8k16 HMMA, f32 acc)
//   out = softplus(relu(D + b2) . W3 + b3)
// NOTE: harness compiles via compute_103 (no 'a') -> no tcgen05/TMEM allowed.
// ---------------------------------------------------------------------------

#define MAXN 100000

__device__ float g_PQ[(size_t)MAXN * 256];
__device__ float g_C[13 * 128];
__device__ int   g_ei_is64;
__device__ int   g_bt_is64;

__device__ __forceinline__ uint32_t smem_u32(const void* p) {
    uint32_t a;
    asm("{ .reg .u64 t; cvta.to.shared.u64 t, %1; cvt.u32.u64 %0, t; }"
        : "=r"(a) : "l"(p));
    return a;
}

__device__ __forceinline__ void ldsm_x4(uint32_t* r, uint32_t addr) {
    asm volatile("ldmatrix.sync.aligned.m8n8.x4.shared.b16 {%0,%1,%2,%3}, [%4];"
                 : "=r"(r[0]), "=r"(r[1]), "=r"(r[2]), "=r"(r[3]) : "r"(addr));
}

__device__ __forceinline__ void mma_bf16(float* d, const uint32_t* a,
                                         uint32_t b0, uint32_t b1) {
    asm volatile("mma.sync.aligned.m16n8k16.row.col.f32.bf16.bf16.f32 "
                 "{%0,%1,%2,%3}, {%4,%5,%6,%7}, {%8,%9}, {%0,%1,%2,%3};"
                 : "+f"(d[0]), "+f"(d[1]), "+f"(d[2]), "+f"(d[3])
                 : "r"(a[0]), "r"(a[1]), "r"(a[2]), "r"(a[3]),
                   "r"(b0), "r"(b1));
}

__device__ __forceinline__ float softplus_f(float x) {
    return fmaxf(x, 0.0f) + log1pf(expf(-fabsf(x)));
}

// ===========================================================================
__global__ void detect_dtype_kernel(const int* __restrict__ ei,
                                    const int* __restrict__ bt) {
    if (threadIdx.x == 0 && blockIdx.x == 0) {
        int e64 = 1, b64 = 1;
        #pragma unroll 1
        for (int i = 0; i < 64; i++) if (ei[2 * i + 1] != 0) { e64 = 0; break; }
        #pragma unroll 1
        for (int i = 0; i < 64; i++) if (bt[2 * i + 1] != 0) { b64 = 0; break; }
        g_ei_is64 = e64;
        g_bt_is64 = b64;
    }
}

__global__ void cemb_kernel(const float* __restrict__ embed,
                            const float* __restrict__ W1,
                            const float* __restrict__ b1) {
    int idx = blockIdx.x * 256 + threadIdx.x;
    if (idx < 13 * 128) {
        int t = idx >> 7, j = idx & 127;
        float s = b1[j];
        #pragma unroll
        for (int k = 0; k < 32; k++)
            s = fmaf(embed[t * 32 + k], W1[(256 + k) * 128 + j], s);
        g_C[idx] = s;
    }
}

// ===========================================================================
// Node GEMM on mma.sync: PQ[n] = z[n] @ [W1_top | W1_mid]
// Persistent: 296 CTAs; CTA<148 -> P half (W1 rows 0:128), else Q half.
// Per tile: 64 nodes x 128 out-cols, k=128, 3-term bf16 split.
// ===========================================================================
#define NROWB 272
#define NOFF_AHI 0
#define NOFF_ALO (64 * NROWB)                   // 17408
#define NOFF_WHI (2 * 64 * NROWB)               // 34816
#define NOFF_WLO (2 * 64 * NROWB + 128 * NROWB) // 69632
#define NODE_SMEM (2 * 64 * NROWB + 2 * 128 * NROWB)  // 104448

__global__ void __launch_bounds__(256, 2)
node_mma_kernel(const float* __restrict__ z,
                const float* __restrict__ W1,
                int nNodes, int nTilesN)
{
    extern __shared__ char sb[];
    const uint32_t base = smem_u32(sb);
    char* Ahi = sb + NOFF_AHI;
    char* Alo = sb + NOFF_ALO;
    char* Whi = sb + NOFF_WHI;
    char* Wlo = sb + NOFF_WLO;

    const int tid  = threadIdx.x;
    const int wid  = tid >> 5;
    const int lane = tid & 31;
    const int g    = lane >> 2;
    const int tg   = lane & 3;

    const int halfStride = gridDim.x >> 1;            // 148
    const int half = (blockIdx.x >= halfStride) ? 1 : 0;
    const int t0   = blockIdx.x - half * halfStride;
    const int krow = half * 128;

    // ---- stage W1T half (n=128 rows, k=128), split bf16 hi/lo (once) ----
    for (int i = tid; i < 128 * 128; i += 256) {
        int k = i >> 7, n = i & 127;
        float w = W1[(krow + k) * 128 + n];
        __nv_bfloat16 hi = __float2bfloat16(w);
        float lof = w - __bfloat162float(hi);
        uint32_t off = (uint32_t)n * NROWB + (uint32_t)k * 2;
        *(__nv_bfloat16*)(Whi + off) = hi;
        *(__nv_bfloat16*)(Wlo + off) = __float2bfloat16(lof);
    }

    const uint32_t rowoff = (uint32_t)(((lane & 7) + ((lane & 8) ? 8 : 0)) * NROWB
                                       + ((lane & 16) ? 16 : 0));
    const int mt = wid & 3;          // m16 tile: nodes mt*16..+15
    const int ng = (wid >> 2) * 64;  // n group: out cols ng..ng+63
    const uint32_t aHiB = base + NOFF_AHI + (uint32_t)(mt * 16) * NROWB + rowoff;
    const uint32_t aLoB = base + NOFF_ALO + (uint32_t)(mt * 16) * NROWB + rowoff;
    const uint32_t wHiB = base + NOFF_WHI + (uint32_t)ng * NROWB + rowoff;
    const uint32_t wLoB = base + NOFF_WLO + (uint32_t)ng * NROWB + rowoff;

    const float4* z4 = (const float4*)z;

    for (int t = t0; t < nTilesN; t += halfStride) {
        const int nb = t * 64;
        __syncthreads();   // prior tile's ldsm complete before overwriting A

        // ---- stage A: 64 nodes x 128 k, split bf16 ----
        #pragma unroll 2
        for (int idx = tid; idx < 64 * 32; idx += 256) {
            int e = idx >> 5, c = idx & 31;
            float4 v = make_float4(0.f, 0.f, 0.f, 0.f);
            if (nb + e < nNodes) v = z4[(size_t)(nb + e) * 32 + c];
            union { uint2 u; __nv_bfloat16 h[4]; } ph, pl;
            ph.h[0] = __float2bfloat16(v.x);
            ph.h[1] = __float2bfloat16(v.y);
            ph.h[2] = __float2bfloat16(v.z);
            ph.h[3] = __float2bfloat16(v.w);
            pl.h[0] = __float2bfloat16(v.x - __bfloat162float(ph.h[0]));
            pl.h[1] = __float2bfloat16(v.y - __bfloat162float(ph.h[1]));
            pl.h[2] = __float2bfloat16(v.z - __bfloat162float(ph.h[2]));
            pl.h[3] = __float2bfloat16(v.w - __bfloat162float(ph.h[3]));
            uint32_t off = (uint32_t)e * NROWB + (uint32_t)c * 8;
            *(uint2*)(Ahi + off) = ph.u;
            *(uint2*)(Alo + off) = pl.u;
        }
        __syncthreads();

        // ---- MMAs: warp = 16 nodes x 64 cols, k=128 ----
        float D[8][4];
        #pragma unroll
        for (int i = 0; i < 8; i++)
            #pragma unroll
            for (int j = 0; j < 4; j++) D[i][j] = 0.f;

        #pragma unroll
        for (int ks = 0; ks < 8; ks++) {
            uint32_t ah[4], al[4];
            ldsm_x4(ah, aHiB + ks * 32);
            ldsm_x4(al, aLoB + ks * 32);
            #pragma unroll
            for (int p = 0; p < 4; p++) {
                uint32_t bh[4], bl[4];
                ldsm_x4(bh, wHiB + (uint32_t)(p * 16) * NROWB + ks * 32);
                ldsm_x4(bl, wLoB + (uint32_t)(p * 16) * NROWB + ks * 32);
                mma_bf16(D[2 * p],     ah, bh[0], bh[2]);
                mma_bf16(D[2 * p],     ah, bl[0], bl[2]);
                mma_bf16(D[2 * p],     al, bh[0], bh[2]);
                mma_bf16(D[2 * p + 1], ah, bh[1], bh[3]);
                mma_bf16(D[2 * p + 1], ah, bl[1], bl[3]);
                mma_bf16(D[2 * p + 1], al, bh[1], bh[3]);
            }
        }

        // ---- store D -> g_PQ (float2 per n8 tile) ----
        {
            int node0 = nb + mt * 16 + g;
            int cbase = half * 128 + ng + tg * 2;
            if (node0 < nNodes) {
                float* r = &g_PQ[(size_t)node0 * 256 + cbase];
                #pragma unroll
                for (int j = 0; j < 8; j++)
                    *(float2*)(r + j * 8) = make_float2(D[j][0], D[j][1]);
            }
            int node1 = node0 + 8;
            if (node1 < nNodes) {
                float* r = &g_PQ[(size_t)node1 * 256 + cbase];
                #pragma unroll
                for (int j = 0; j < 8; j++)
                    *(float2*)(r + j * 8) = make_float2(D[j][2], D[j][3]);
            }
        }
    }
}

// ===========================================================================
// Edge kernel: persistent, mma.sync layer 2 (unchanged from R4 pass)
// ===========================================================================
#define ETILE  128
#define ROWB   272
#define OFF_AHI  0
#define OFF_ALO  (OFF_AHI + 128 * ROWB)
#define OFF_WHI  (OFF_ALO + 128 * ROWB)
#define OFF_WLO  (OFF_WHI + 64 * ROWB)
#define OFF_C    (OFF_WLO + 64 * ROWB)
#define OFF_BW   (OFF_C + 13 * 128 * 4)
#define OFF_IDX  (OFF_BW + 64 * 8)
#define EDGE_SMEM (OFF_IDX + 3 * ETILE * 4)

__global__ void __launch_bounds__(256, 2)
edge_mma_kernel(const void*  __restrict__ eiv,
                const void*  __restrict__ btv,
                const float* __restrict__ W2,
                const float* __restrict__ b2,
                const float* __restrict__ W3,
                const float* __restrict__ b3,
                float* __restrict__ out,
                int E, int nTiles)
{
    extern __shared__ char sb[];
    const uint32_t base = smem_u32(sb);

    char*   Ahi = sb + OFF_AHI;
    char*   Alo = sb + OFF_ALO;
    char*   Whi = sb + OFF_WHI;
    char*   Wlo = sb + OFF_WLO;
    float*  sC  = (float*)(sb + OFF_C);
    float2* sBW = (float2*)(sb + OFF_BW);
    int*    sSrc = (int*)(sb + OFF_IDX);
    int*    sDst = sSrc + ETILE;
    int*    sBt  = sDst + ETILE;

    const int tid  = threadIdx.x;
    const int wid  = tid >> 5;
    const int lane = tid & 31;
    const int g    = lane >> 2;
    const int tg   = lane & 3;
    const int ei64 = g_ei_is64, bt64 = g_bt_is64;

    for (int i = tid; i < 13 * 32; i += 256)
        ((float4*)sC)[i] = ((const float4*)g_C)[i];
    if (tid < 64) sBW[tid] = make_float2(b2[tid], W3[tid]);
    for (int i = tid; i < 128 * 64; i += 256) {
        int k = i >> 6, n = i & 63;
        float w = W2[i];
        __nv_bfloat16 hi = __float2bfloat16(w);
        float lof = w - __bfloat162float(hi);
        uint32_t off = (uint32_t)n * ROWB + (uint32_t)k * 2;
        *(__nv_bfloat16*)(Whi + off) = hi;
        *(__nv_bfloat16*)(Wlo + off) = __float2bfloat16(lof);
    }
    __syncthreads();

    const float b3v = __ldg(b3);

    const uint32_t rowoff = (uint32_t)(((lane & 7) + ((lane & 8) ? 8 : 0)) * ROWB
                                       + ((lane & 16) ? 16 : 0));
    const uint32_t aHiBase = base + OFF_AHI + (uint32_t)(wid * 16) * ROWB + rowoff;
    const uint32_t aLoBase = base + OFF_ALO + (uint32_t)(wid * 16) * ROWB + rowoff;
    const uint32_t wHiBase = base + OFF_WHI + rowoff;
    const uint32_t wLoBase = base + OFF_WLO + rowoff;

    const float4* PQ4 = (const float4*)g_PQ;

    for (int tile = blockIdx.x; tile < nTiles; tile += gridDim.x) {
        const int eBase = tile * ETILE;

        if (tid < ETILE) {
            int e = eBase + tid;
            int s = 0, d = 0, b = 0;
            if (e < E) {
                if (ei64) {
                    const long long* p = (const long long*)eiv;
                    s = (int)p[e]; d = (int)p[(size_t)E + e];
                } else {
                    const int* p = (const int*)eiv;
                    s = p[e]; d = p[(size_t)E + e];
                }
                if (bt64) b = (int)((const long long*)btv)[e];
                else      b = ((const int*)btv)[e];
            }
            sSrc[tid] = s; sDst[tid] = d; sBt[tid] = b;
        }
        __syncthreads();

        #pragma unroll 4
        for (int idx = tid; idx < ETILE * 32; idx += 256) {
            int e = idx >> 5, c = idx & 31;
            float4 p = PQ4[(size_t)sSrc[e] * 64 + c];
            float4 q = PQ4[(size_t)sDst[e] * 64 + 32 + c];
            float4 cc = ((const float4*)(sC + sBt[e] * 128))[c];
            float g0 = fmaxf(p.x + q.x + cc.x, 0.f);
            float g1 = fmaxf(p.y + q.y + cc.y, 0.f);
            float g2 = fmaxf(p.z + q.z + cc.z, 0.f);
            float g3 = fmaxf(p.w + q.w + cc.w, 0.f);
            union { uint2 u; __nv_bfloat16 h[4]; } ph, pl;
            ph.h[0] = __float2bfloat16(g0);
            ph.h[1] = __float2bfloat16(g1);
            ph.h[2] = __float2bfloat16(g2);
            ph.h[3] = __float2bfloat16(g3);
            pl.h[0] = __float2bfloat16(g0 - __bfloat162float(ph.h[0]));
            pl.h[1] = __float2bfloat16(g1 - __bfloat162float(ph.h[1]));
            pl.h[2] = __float2bfloat16(g2 - __bfloat162float(ph.h[2]));
            pl.h[3] = __float2bfloat16(g3 - __bfloat162float(ph.h[3]));
            uint32_t off = (uint32_t)e * ROWB + (uint32_t)c * 8;
            *(uint2*)(Ahi + off) = ph.u;
            *(uint2*)(Alo + off) = pl.u;
        }
        __syncthreads();

        float D[8][4];
        #pragma unroll
        for (int i = 0; i < 8; i++)
            #pragma unroll
            for (int j = 0; j < 4; j++) D[i][j] = 0.f;

        #pragma unroll
        for (int ks = 0; ks < 8; ks++) {
            uint32_t ah[4], al[4];
            ldsm_x4(ah, aHiBase + ks * 32);
            ldsm_x4(al, aLoBase + ks * 32);
            #pragma unroll
            for (int p = 0; p < 4; p++) {
                uint32_t bh[4], bl[4];
                ldsm_x4(bh, wHiBase + (uint32_t)(p * 16) * ROWB + ks * 32);
                ldsm_x4(bl, wLoBase + (uint32_t)(p * 16) * ROWB + ks * 32);
                mma_bf16(D[2 * p],     ah, bh[0], bh[2]);
                mma_bf16(D[2 * p],     ah, bl[0], bl[2]);
                mma_bf16(D[2 * p],     al, bh[0], bh[2]);
                mma_bf16(D[2 * p + 1], ah, bh[1], bh[3]);
                mma_bf16(D[2 * p + 1], ah, bl[1], bl[3]);
                mma_bf16(D[2 * p + 1], al, bh[1], bh[3]);
            }
        }

        {
            float p0 = 0.f, p1 = 0.f;
            #pragma unroll
            for (int nt = 0; nt < 8; nt++) {
                int n = nt * 8 + tg * 2;
                float2 bw0 = sBW[n];
                float2 bw1 = sBW[n + 1];
                p0 = fmaf(fmaxf(D[nt][0] + bw0.x, 0.f), bw0.y, p0);
                p0 = fmaf(fmaxf(D[nt][1] + bw1.x, 0.f), bw1.y, p0);
                p1 = fmaf(fmaxf(D[nt][2] + bw0.x, 0.f), bw0.y, p1);
                p1 = fmaf(fmaxf(D[nt][3] + bw1.x, 0.f), bw1.y, p1);
            }
            p0 += __shfl_xor_sync(0xffffffffu, p0, 1);
            p0 += __shfl_xor_sync(0xffffffffu, p0, 2);
            p1 += __shfl_xor_sync(0xffffffffu, p1, 1);
            p1 += __shfl_xor_sync(0xffffffffu, p1, 2);
            if (tg == 0) {
                int e0 = eBase + wid * 16 + g;
                if (e0 < E)     out[e0]     = softplus_f(p0 + b3v);
                if (e0 + 8 < E) out[e0 + 8] = softplus_f(p1 + b3v);
            }
        }
        __syncthreads();
    }
}

// ===========================================================================
extern "C" void kernel_launch(void* const* d_in, const int* in_sizes, int n_in,
                              void* d_out, int out_size)
{
    const float* z     = (const float*)d_in[0];
    const void*  ei    = d_in[1];
    const void*  bt    = d_in[2];
    const float* embed = (const float*)d_in[3];
    const float* W1    = (const float*)d_in[4];
    const float* b1    = (const float*)d_in[5];
    const float* W2    = (const float*)d_in[6];
    const float* b2    = (const float*)d_in[7];
    const float* W3    = (const float*)d_in[8];
    const float* b3    = (const float*)d_in[9];
    float* out = (float*)d_out;

    int nNodes = in_sizes[0] / 128;
    int E = out_size;
    int nTiles  = (E + ETILE - 1) / ETILE;
    int nTilesN = (nNodes + 63) / 64;

    static int attr_done = 0;
    if (!attr_done) {
        cudaFuncSetAttribute(node_mma_kernel,
                             cudaFuncAttributeMaxDynamicSharedMemorySize, NODE_SMEM);
        cudaFuncSetAttribute(edge_mma_kernel,
                             cudaFuncAttributeMaxDynamicSharedMemorySize, EDGE_SMEM);
        attr_done = 1;
    }

    detect_dtype_kernel<<<1, 32>>>((const int*)ei, (const int*)bt);
    cemb_kernel<<<7, 256>>>(embed, W1, b1);

    node_mma_kernel<<<296, 256, NODE_SMEM>>>(z, W1, nNodes, nTilesN);

    int eg = nTiles < 296 ? nTiles : 296;
    edge_mma_kernel<<<eg, 256, EDGE_SMEM>>>(ei, bt, W2, b2, W3, b3, out, E, nTiles);
}

// round 10
// speedup vs baseline: 9.9765x; 1.4228x over previous
#include <cuda_runtime.h>
#include <cuda_bf16.h>
#include <math.h>
#include <stdint.h>

// ---------------------------------------------------------------------------
// BondLengthHead, fully tensorized (mma.sync bf16 split, f32 accum):
//   P = z @ W1[0:128,:], Q = z @ W1[128:256,:]   (node_mma_kernel, HMMA)
//   C = embed @ W1[256:288,:] + b1               (13x128)
//   edge kernel: warp-autonomous 16-edge pipelines, no CTA barriers in loop:
//     g = relu(P[src]+Q[dst]+C[bt]) -> split bf16 hi/lo
//     D = Ahi Bhi + Ahi Blo + Alo Bhi  (m16n8k16 HMMA, f32 acc)
//     out = softplus(relu(D + b2) . W3 + b3)
// NOTE: harness compiles via compute_103 (no 'a') -> no tcgen05/TMEM allowed.
// ---------------------------------------------------------------------------

#define MAXN 100000

__device__ float g_PQ[(size_t)MAXN * 256];
__device__ float g_C[13 * 128];
__device__ int   g_ei_is64;
__device__ int   g_bt_is64;

__device__ __forceinline__ uint32_t smem_u32(const void* p) {
    uint32_t a;
    asm("{ .reg .u64 t; cvta.to.shared.u64 t, %1; cvt.u32.u64 %0, t; }"
        : "=r"(a) : "l"(p));
    return a;
}

__device__ __forceinline__ void ldsm_x4(uint32_t* r, uint32_t addr) {
    asm volatile("ldmatrix.sync.aligned.m8n8.x4.shared.b16 {%0,%1,%2,%3}, [%4];"
                 : "=r"(r[0]), "=r"(r[1]), "=r"(r[2]), "=r"(r[3]) : "r"(addr));
}

__device__ __forceinline__ void mma_bf16(float* d, const uint32_t* a,
                                         uint32_t b0, uint32_t b1) {
    asm volatile("mma.sync.aligned.m16n8k16.row.col.f32.bf16.bf16.f32 "
                 "{%0,%1,%2,%3}, {%4,%5,%6,%7}, {%8,%9}, {%0,%1,%2,%3};"
                 : "+f"(d[0]), "+f"(d[1]), "+f"(d[2]), "+f"(d[3])
                 : "r"(a[0]), "r"(a[1]), "r"(a[2]), "r"(a[3]),
                   "r"(b0), "r"(b1));
}

__device__ __forceinline__ float softplus_f(float x) {
    return fmaxf(x, 0.0f) + log1pf(expf(-fabsf(x)));
}

// ===========================================================================
__global__ void detect_dtype_kernel(const int* __restrict__ ei,
                                    const int* __restrict__ bt) {
    if (threadIdx.x == 0 && blockIdx.x == 0) {
        int e64 = 1, b64 = 1;
        #pragma unroll 1
        for (int i = 0; i < 64; i++) if (ei[2 * i + 1] != 0) { e64 = 0; break; }
        #pragma unroll 1
        for (int i = 0; i < 64; i++) if (bt[2 * i + 1] != 0) { b64 = 0; break; }
        g_ei_is64 = e64;
        g_bt_is64 = b64;
    }
}

__global__ void cemb_kernel(const float* __restrict__ embed,
                            const float* __restrict__ W1,
                            const float* __restrict__ b1) {
    int idx = blockIdx.x * 256 + threadIdx.x;
    if (idx < 13 * 128) {
        int t = idx >> 7, j = idx & 127;
        float s = b1[j];
        #pragma unroll
        for (int k = 0; k < 32; k++)
            s = fmaf(embed[t * 32 + k], W1[(256 + k) * 128 + j], s);
        g_C[idx] = s;
    }
}

// ===========================================================================
// Node GEMM on mma.sync (unchanged from R5 pass)
// ===========================================================================
#define NROWB 272
#define NOFF_AHI 0
#define NOFF_ALO (64 * NROWB)
#define NOFF_WHI (2 * 64 * NROWB)
#define NOFF_WLO (2 * 64 * NROWB + 128 * NROWB)
#define NODE_SMEM (2 * 64 * NROWB + 2 * 128 * NROWB)

__global__ void __launch_bounds__(256, 2)
node_mma_kernel(const float* __restrict__ z,
                const float* __restrict__ W1,
                int nNodes, int nTilesN)
{
    extern __shared__ char sb[];
    const uint32_t base = smem_u32(sb);
    char* Ahi = sb + NOFF_AHI;
    char* Alo = sb + NOFF_ALO;
    char* Whi = sb + NOFF_WHI;
    char* Wlo = sb + NOFF_WLO;

    const int tid  = threadIdx.x;
    const int wid  = tid >> 5;
    const int lane = tid & 31;
    const int g    = lane >> 2;
    const int tg   = lane & 3;

    const int halfStride = gridDim.x >> 1;
    const int half = (blockIdx.x >= halfStride) ? 1 : 0;
    const int t0   = blockIdx.x - half * halfStride;
    const int krow = half * 128;

    for (int i = tid; i < 128 * 128; i += 256) {
        int k = i >> 7, n = i & 127;
        float w = W1[(krow + k) * 128 + n];
        __nv_bfloat16 hi = __float2bfloat16(w);
        float lof = w - __bfloat162float(hi);
        uint32_t off = (uint32_t)n * NROWB + (uint32_t)k * 2;
        *(__nv_bfloat16*)(Whi + off) = hi;
        *(__nv_bfloat16*)(Wlo + off) = __float2bfloat16(lof);
    }

    const uint32_t rowoff = (uint32_t)(((lane & 7) + ((lane & 8) ? 8 : 0)) * NROWB
                                       + ((lane & 16) ? 16 : 0));
    const int mt = wid & 3;
    const int ng = (wid >> 2) * 64;
    const uint32_t aHiB = base + NOFF_AHI + (uint32_t)(mt * 16) * NROWB + rowoff;
    const uint32_t aLoB = base + NOFF_ALO + (uint32_t)(mt * 16) * NROWB + rowoff;
    const uint32_t wHiB = base + NOFF_WHI + (uint32_t)ng * NROWB + rowoff;
    const uint32_t wLoB = base + NOFF_WLO + (uint32_t)ng * NROWB + rowoff;

    const float4* z4 = (const float4*)z;

    for (int t = t0; t < nTilesN; t += halfStride) {
        const int nb = t * 64;
        __syncthreads();

        #pragma unroll 2
        for (int idx = tid; idx < 64 * 32; idx += 256) {
            int e = idx >> 5, c = idx & 31;
            float4 v = make_float4(0.f, 0.f, 0.f, 0.f);
            if (nb + e < nNodes) v = z4[(size_t)(nb + e) * 32 + c];
            union { uint2 u; __nv_bfloat16 h[4]; } ph, pl;
            ph.h[0] = __float2bfloat16(v.x);
            ph.h[1] = __float2bfloat16(v.y);
            ph.h[2] = __float2bfloat16(v.z);
            ph.h[3] = __float2bfloat16(v.w);
            pl.h[0] = __float2bfloat16(v.x - __bfloat162float(ph.h[0]));
            pl.h[1] = __float2bfloat16(v.y - __bfloat162float(ph.h[1]));
            pl.h[2] = __float2bfloat16(v.z - __bfloat162float(ph.h[2]));
            pl.h[3] = __float2bfloat16(v.w - __bfloat162float(ph.h[3]));
            uint32_t off = (uint32_t)e * NROWB + (uint32_t)c * 8;
            *(uint2*)(Ahi + off) = ph.u;
            *(uint2*)(Alo + off) = pl.u;
        }
        __syncthreads();

        float D[8][4];
        #pragma unroll
        for (int i = 0; i < 8; i++)
            #pragma unroll
            for (int j = 0; j < 4; j++) D[i][j] = 0.f;

        #pragma unroll
        for (int ks = 0; ks < 8; ks++) {
            uint32_t ah[4], al[4];
            ldsm_x4(ah, aHiB + ks * 32);
            ldsm_x4(al, aLoB + ks * 32);
            #pragma unroll
            for (int p = 0; p < 4; p++) {
                uint32_t bh[4], bl[4];
                ldsm_x4(bh, wHiB + (uint32_t)(p * 16) * NROWB + ks * 32);
                ldsm_x4(bl, wLoB + (uint32_t)(p * 16) * NROWB + ks * 32);
                mma_bf16(D[2 * p],     ah, bh[0], bh[2]);
                mma_bf16(D[2 * p],     ah, bl[0], bl[2]);
                mma_bf16(D[2 * p],     al, bh[0], bh[2]);
                mma_bf16(D[2 * p + 1], ah, bh[1], bh[3]);
                mma_bf16(D[2 * p + 1], ah, bl[1], bl[3]);
                mma_bf16(D[2 * p + 1], al, bh[1], bh[3]);
            }
        }

        {
            int node0 = nb + mt * 16 + g;
            int cbase = half * 128 + ng + tg * 2;
            if (node0 < nNodes) {
                float* r = &g_PQ[(size_t)node0 * 256 + cbase];
                #pragma unroll
                for (int j = 0; j < 8; j++)
                    *(float2*)(r + j * 8) = make_float2(D[j][0], D[j][1]);
            }
            int node1 = node0 + 8;
            if (node1 < nNodes) {
                float* r = &g_PQ[(size_t)node1 * 256 + cbase];
                #pragma unroll
                for (int j = 0; j < 8; j++)
                    *(float2*)(r + j * 8) = make_float2(D[j][2], D[j][3]);
            }
        }
    }
}

// ===========================================================================
// Edge kernel: warp-autonomous pipelines, no CTA barrier in the tile loop
// ===========================================================================
#define ETILE  128
#define ROWB   272
#define OFF_AHI  0
#define OFF_ALO  (OFF_AHI + 128 * ROWB)
#define OFF_WHI  (OFF_ALO + 128 * ROWB)
#define OFF_WLO  (OFF_WHI + 64 * ROWB)
#define OFF_C    (OFF_WLO + 64 * ROWB)
#define OFF_BW   (OFF_C + 13 * 128 * 4)
#define EDGE_SMEM (OFF_BW + 64 * 8)

__global__ void __launch_bounds__(256, 2)
edge_mma_kernel(const void*  __restrict__ eiv,
                const void*  __restrict__ btv,
                const float* __restrict__ W2,
                const float* __restrict__ b2,
                const float* __restrict__ W3,
                const float* __restrict__ b3,
                float* __restrict__ out,
                int E, int nTiles)
{
    extern __shared__ char sb[];
    const uint32_t base = smem_u32(sb);

    char*   Ahi = sb + OFF_AHI;
    char*   Alo = sb + OFF_ALO;
    char*   Whi = sb + OFF_WHI;
    char*   Wlo = sb + OFF_WLO;
    float*  sC  = (float*)(sb + OFF_C);
    float2* sBW = (float2*)(sb + OFF_BW);

    const int tid  = threadIdx.x;
    const int wid  = tid >> 5;
    const int lane = tid & 31;
    const int g    = lane >> 2;
    const int tg   = lane & 3;
    const int ei64 = g_ei_is64, bt64 = g_bt_is64;

    // ---- one-time staging ----
    for (int i = tid; i < 13 * 32; i += 256)
        ((float4*)sC)[i] = ((const float4*)g_C)[i];
    if (tid < 64) sBW[tid] = make_float2(b2[tid], W3[tid]);
    for (int i = tid; i < 128 * 64; i += 256) {
        int k = i >> 6, n = i & 63;
        float w = W2[i];
        __nv_bfloat16 hi = __float2bfloat16(w);
        float lof = w - __bfloat162float(hi);
        uint32_t off = (uint32_t)n * ROWB + (uint32_t)k * 2;
        *(__nv_bfloat16*)(Whi + off) = hi;
        *(__nv_bfloat16*)(Wlo + off) = __float2bfloat16(lof);
    }
    __syncthreads();

    const float b3v = __ldg(b3);

    const uint32_t rowoff = (uint32_t)(((lane & 7) + ((lane & 8) ? 8 : 0)) * ROWB
                                       + ((lane & 16) ? 16 : 0));
    const uint32_t aHiBase = base + OFF_AHI + (uint32_t)(wid * 16) * ROWB + rowoff;
    const uint32_t aLoBase = base + OFF_ALO + (uint32_t)(wid * 16) * ROWB + rowoff;
    const uint32_t wHiBase = base + OFF_WHI + rowoff;
    const uint32_t wLoBase = base + OFF_WLO + rowoff;

    const float4* PQ4 = (const float4*)g_PQ;
    const float4* sC4 = (const float4*)sC;
    const int laneSel = lane & 15;

    for (int tile = blockIdx.x; tile < nTiles; tile += gridDim.x) {
        const int eW = tile * ETILE + wid * 16;   // this warp's 16 edges

        // ---- indices into registers: lanes 0..15 src, 16..31 dst ----
        int rs, rbt = 0;
        {
            int e = eW + laneSel;
            bool valid = e < E;
            size_t half = (lane < 16) ? 0 : (size_t)E;
            if (ei64) {
                const long long* p = (const long long*)eiv;
                rs = valid ? (int)p[half + e] : 0;
            } else {
                const int* p = (const int*)eiv;
                rs = valid ? p[half + e] : 0;
            }
            if (lane < 16) {
                rbt = valid ? (bt64 ? (int)((const long long*)btv)[e]
                                    : ((const int*)btv)[e]) : 0;
            }
        }
        __syncwarp();

        // ---- gather + relu + split into this warp's private A rows ----
        #pragma unroll
        for (int i = 0; i < 16; i++) {
            int s = __shfl_sync(0xffffffffu, rs, i);
            int d = __shfl_sync(0xffffffffu, rs, 16 + i);
            int b = __shfl_sync(0xffffffffu, rbt, i);
            float4 p  = PQ4[(size_t)s * 64 + lane];
            float4 q  = PQ4[(size_t)d * 64 + 32 + lane];
            float4 cc = sC4[b * 32 + lane];
            float g0 = fmaxf(p.x + q.x + cc.x, 0.f);
            float g1 = fmaxf(p.y + q.y + cc.y, 0.f);
            float g2 = fmaxf(p.z + q.z + cc.z, 0.f);
            float g3 = fmaxf(p.w + q.w + cc.w, 0.f);
            union { uint2 u; __nv_bfloat16 h[4]; } ph, pl;
            ph.h[0] = __float2bfloat16(g0);
            ph.h[1] = __float2bfloat16(g1);
            ph.h[2] = __float2bfloat16(g2);
            ph.h[3] = __float2bfloat16(g3);
            pl.h[0] = __float2bfloat16(g0 - __bfloat162float(ph.h[0]));
            pl.h[1] = __float2bfloat16(g1 - __bfloat162float(ph.h[1]));
            pl.h[2] = __float2bfloat16(g2 - __bfloat162float(ph.h[2]));
            pl.h[3] = __float2bfloat16(g3 - __bfloat162float(ph.h[3]));
            uint32_t off = (uint32_t)(wid * 16 + i) * ROWB + (uint32_t)lane * 8;
            *(uint2*)(Ahi + off) = ph.u;
            *(uint2*)(Alo + off) = pl.u;
        }
        __syncwarp();

        // ---- layer 2 MMAs: 16 edges x 64 n, k=128, 3-term split ----
        float D[8][4];
        #pragma unroll
        for (int i = 0; i < 8; i++)
            #pragma unroll
            for (int j = 0; j < 4; j++) D[i][j] = 0.f;

        #pragma unroll
        for (int ks = 0; ks < 8; ks++) {
            uint32_t ah[4], al[4];
            ldsm_x4(ah, aHiBase + ks * 32);
            ldsm_x4(al, aLoBase + ks * 32);
            #pragma unroll
            for (int p = 0; p < 4; p++) {
                uint32_t bh[4], bl[4];
                ldsm_x4(bh, wHiBase + (uint32_t)(p * 16) * ROWB + ks * 32);
                ldsm_x4(bl, wLoBase + (uint32_t)(p * 16) * ROWB + ks * 32);
                mma_bf16(D[2 * p],     ah, bh[0], bh[2]);
                mma_bf16(D[2 * p],     ah, bl[0], bl[2]);
                mma_bf16(D[2 * p],     al, bh[0], bh[2]);
                mma_bf16(D[2 * p + 1], ah, bh[1], bh[3]);
                mma_bf16(D[2 * p + 1], ah, bl[1], bl[3]);
                mma_bf16(D[2 * p + 1], al, bh[1], bh[3]);
            }
        }

        // ---- layer 3 + softplus ----
        {
            float p0 = 0.f, p1 = 0.f;
            #pragma unroll
            for (int nt = 0; nt < 8; nt++) {
                int n = nt * 8 + tg * 2;
                float2 bw0 = sBW[n];
                float2 bw1 = sBW[n + 1];
                p0 = fmaf(fmaxf(D[nt][0] + bw0.x, 0.f), bw0.y, p0);
                p0 = fmaf(fmaxf(D[nt][1] + bw1.x, 0.f), bw1.y, p0);
                p1 = fmaf(fmaxf(D[nt][2] + bw0.x, 0.f), bw0.y, p1);
                p1 = fmaf(fmaxf(D[nt][3] + bw1.x, 0.f), bw1.y, p1);
            }
            p0 += __shfl_xor_sync(0xffffffffu, p0, 1);
            p0 += __shfl_xor_sync(0xffffffffu, p0, 2);
            p1 += __shfl_xor_sync(0xffffffffu, p1, 1);
            p1 += __shfl_xor_sync(0xffffffffu, p1, 2);
            if (tg == 0) {
                int e0 = eW + g;
                if (e0 < E)     out[e0]     = softplus_f(p0 + b3v);
                if (e0 + 8 < E) out[e0 + 8] = softplus_f(p1 + b3v);
            }
        }
        // next iteration's __syncwarp orders A reuse; no CTA barrier needed
    }
}

// ===========================================================================
extern "C" void kernel_launch(void* const* d_in, const int* in_sizes, int n_in,
                              void* d_out, int out_size)
{
    const float* z     = (const float*)d_in[0];
    const void*  ei    = d_in[1];
    const void*  bt    = d_in[2];
    const float* embed = (const float*)d_in[3];
    const float* W1    = (const float*)d_in[4];
    const float* b1    = (const float*)d_in[5];
    const float* W2    = (const float*)d_in[6];
    const float* b2    = (const float*)d_in[7];
    const float* W3    = (const float*)d_in[8];
    const float* b3    = (const float*)d_in[9];
    float* out = (float*)d_out;

    int nNodes = in_sizes[0] / 128;
    int E = out_size;
    int nTiles  = (E + ETILE - 1) / ETILE;
    int nTilesN = (nNodes + 63) / 64;

    static int attr_done = 0;
    if (!attr_done) {
        cudaFuncSetAttribute(node_mma_kernel,
                             cudaFuncAttributeMaxDynamicSharedMemorySize, NODE_SMEM);
        cudaFuncSetAttribute(edge_mma_kernel,
                             cudaFuncAttributeMaxDynamicSharedMemorySize, EDGE_SMEM);
        attr_done = 1;
    }

    detect_dtype_kernel<<<1, 32>>>((const int*)ei, (const int*)bt);
    cemb_kernel<<<7, 256>>>(embed, W1, b1);

    node_mma_kernel<<<296, 256, NODE_SMEM>>>(z, W1, nNodes, nTilesN);

    int eg = nTiles < 296 ? nTiles : 296;
    edge_mma_kernel<<<eg, 256, EDGE_SMEM>>>(ei, bt, W2, b2, W3, b3, out, E, nTiles);
}